// round 14
// baseline (speedup 1.0000x reference)
#include <cuda_runtime.h>

#define N   128
#define N3  (N*N*N)

// BU BV BW U1 V1 W1 B P1 (8 x N3) + Rp1(64^3) + Rp2(32^3) + W32(32^3) + Rp3(2x16^3)
__device__ float g_scratch[8 * (size_t)N3 + 262144 + 2 * 32768 + 8192];

static __device__ __forceinline__ int cl(int x) { return x < 0 ? 0 : (x > N - 1 ? N - 1 : x); }
static __device__ __forceinline__ int ix(int d, int h, int w) { return (d << 14) + (h << 7) + w; }

static __device__ __forceinline__ float4 ld4(const float* __restrict__ p, int i) {
    return *reinterpret_cast<const float4*>(p + i);
}
static __device__ __forceinline__ void st4(float* __restrict__ p, int i, float4 v) {
    *reinterpret_cast<float4*>(p + i) = v;
}
static __device__ __forceinline__ float4 operator+(float4 a, float4 b) { return make_float4(a.x+b.x, a.y+b.y, a.z+b.z, a.w+b.w); }
static __device__ __forceinline__ float4 operator-(float4 a, float4 b) { return make_float4(a.x-b.x, a.y-b.y, a.z-b.z, a.w-b.w); }
static __device__ __forceinline__ float4 operator*(float s, float4 a) { return make_float4(s*a.x, s*a.y, s*a.z, s*a.w); }
static __device__ __forceinline__ float4 operator*(float4 a, float4 b) { return make_float4(a.x*b.x, a.y*b.y, a.z*b.z, a.w*b.w); }

struct S7 { float4 c, n, s, b, t; float wl, wr; };

static __device__ __forceinline__ S7 ld7(const float* __restrict__ A,
                                         int cb, int nb, int sb, int bb, int tb, int w4) {
    S7 r;
    r.c = ld4(A, cb); r.n = ld4(A, nb); r.s = ld4(A, sb); r.b = ld4(A, bb); r.t = ld4(A, tb);
    r.wl = (w4 > 0)   ? A[cb - 1] : r.c.x;
    r.wr = (w4 < 124) ? A[cb + 4] : r.c.w;
    return r;
}
static __device__ __forceinline__ float4 westv(const S7& s) { return make_float4(s.wl, s.c.x, s.c.y, s.c.z); }
static __device__ __forceinline__ float4 eastv(const S7& s) { return make_float4(s.c.y, s.c.z, s.c.w, s.wr); }

static __device__ __forceinline__ float4 rcp4(float dt, float4 g) {
    return make_float4(1.f/(1.f+dt*g.x), 1.f/(1.f+dt*g.y), 1.f/(1.f+dt*g.z), 1.f/(1.f+dt*g.w));
}
static __device__ __forceinline__ void scale7(S7& u, const S7& f) {
    u.c = u.c * f.c; u.n = u.n * f.n; u.s = u.s * f.s; u.b = u.b * f.b; u.t = u.t * f.t;
    u.wl *= f.wl; u.wr *= f.wr;
}

#define IDX6(dd)                                      \
    const int d = (dd);                               \
    const int dB = cl(d - 1), dT = cl(d + 1);         \
    const int cb = ix(d, h, w4);                      \
    const int nb = ix(d, hN, w4), sb = ix(d, hS, w4); \
    const int bb = ix(dB, h, w4), tb = ix(dT, h, w4);

// ---------------------------------------------------------------------------
__global__ void __launch_bounds__(128) k_predictor(
    const float* __restrict__ U, const float* __restrict__ V, const float* __restrict__ W_,
    const float* __restrict__ P, const float* __restrict__ SG, const float* __restrict__ DT,
    float* __restrict__ BU, float* __restrict__ BV, float* __restrict__ BW)
{
    const int w4 = threadIdx.x << 2;
    const int h  = (blockIdx.y << 2) + threadIdx.y;
    const int hS = cl(h - 1), hN = cl(h + 1);
    IDX6(blockIdx.z);

    S7 g  = ld7(SG, cb, nb, sb, bb, tb, w4);
    S7 p  = ld7(P,  cb, nb, sb, bb, tb, w4);
    S7 su = ld7(U,  cb, nb, sb, bb, tb, w4);
    S7 sv = ld7(V,  cb, nb, sb, bb, tb, w4);
    S7 sw = ld7(W_, cb, nb, sb, bb, tb, w4);
    const float dt = DT[0];

    S7 f;
    f.c = rcp4(dt, g.c); f.n = rcp4(dt, g.n); f.s = rcp4(dt, g.s);
    f.b = rcp4(dt, g.b); f.t = rcp4(dt, g.t);
    f.wl = 1.f/(1.f+dt*g.wl); f.wr = 1.f/(1.f+dt*g.wr);

    scale7(su, f); scale7(sv, f); scale7(sw, f);
    const float4 uc = su.c, vc = sv.c, wc = sw.c;

    float4 gpx = 0.5f * (eastv(p) - westv(p));
    float4 gpy = 0.5f * (p.n - p.s);
    float4 gpz = 0.5f * (p.t - p.b);

    {
        float4 west = westv(su); if (w4 == 0) west.x = 1.0f;
        float4 east = eastv(su);
        float4 lap = west + east + su.n + su.s + su.b + su.t - 6.f * su.c;
        float4 ax = 0.5f * (east - west), ay = 0.5f * (su.n - su.s), az = 0.5f * (su.t - su.b);
        st4(BU, cb, (uc + 0.5f*dt*(lap - uc*ax - vc*ay - wc*az) - dt*gpx) * f.c);
    }
    {
        float4 west = westv(sv), east = eastv(sv);
        float4 lap = west + east + sv.n + sv.s + sv.b + sv.t - 6.f * sv.c;
        float4 ax = 0.5f * (east - west), ay = 0.5f * (sv.n - sv.s), az = 0.5f * (sv.t - sv.b);
        st4(BV, cb, (vc + 0.5f*dt*(lap - uc*ax - vc*ay - wc*az) - dt*gpy) * f.c);
    }
    {
        float4 west = westv(sw), east = eastv(sw);
        float4 lap = west + east + sw.n + sw.s + sw.b + sw.t - 6.f * sw.c;
        float4 ax = 0.5f * (east - west), ay = 0.5f * (sw.n - sw.s), az = 0.5f * (sw.t - sw.b);
        st4(BW, cb, (wc + 0.5f*dt*(lap - uc*ax - vc*ay - wc*az) - dt*gpz) * f.c);
    }
}

// ---------------------------------------------------------------------------
__global__ void __launch_bounds__(128) k_corrector(
    const float* __restrict__ BU, const float* __restrict__ BV, const float* __restrict__ BW,
    const float* __restrict__ U, const float* __restrict__ V, const float* __restrict__ W_,
    const float* __restrict__ P, const float* __restrict__ SG, const float* __restrict__ DT,
    float* __restrict__ U1, float* __restrict__ V1, float* __restrict__ W1)
{
    const int w4 = threadIdx.x << 2;
    const int h  = (blockIdx.y << 2) + threadIdx.y;
    const int hS = cl(h - 1), hN = cl(h + 1);
    IDX6(blockIdx.z);

    const float4 sg = ld4(SG, cb);
    const float4 Uc = ld4(U, cb), Vc = ld4(V, cb), Wc = ld4(W_, cb);
    S7 p = ld7(P,  cb, nb, sb, bb, tb, w4);
    S7 a = ld7(BU, cb, nb, sb, bb, tb, w4);
    S7 b = ld7(BV, cb, nb, sb, bb, tb, w4);
    S7 c = ld7(BW, cb, nb, sb, bb, tb, w4);
    const float dt = DT[0];

    const float4 fc = rcp4(dt, sg);
    const float4 uc = Uc * fc, vc = Vc * fc, wc = Wc * fc;
    const float4 buc = a.c, bvc = b.c, bwc = c.c;

    float4 gpx = 0.5f * (eastv(p) - westv(p));
    float4 gpy = 0.5f * (p.n - p.s);
    float4 gpz = 0.5f * (p.t - p.b);

    {
        float4 west = westv(a); if (w4 == 0) west.x = 1.0f;
        float4 east = eastv(a);
        float4 lap = west + east + a.n + a.s + a.b + a.t - 6.f * a.c;
        float4 ax = 0.5f * (east - west), ay = 0.5f * (a.n - a.s), az = 0.5f * (a.t - a.b);
        st4(U1, cb, (uc + dt*(lap - buc*ax - bvc*ay - bwc*az) - dt*gpx) * fc);
    }
    {
        float4 west = westv(b), east = eastv(b);
        float4 lap = west + east + b.n + b.s + b.b + b.t - 6.f * b.c;
        float4 ax = 0.5f * (east - west), ay = 0.5f * (b.n - b.s), az = 0.5f * (b.t - b.b);
        st4(V1, cb, (vc + dt*(lap - buc*ax - bvc*ay - bwc*az) - dt*gpy) * fc);
    }
    {
        float4 west = westv(c), east = eastv(c);
        float4 lap = west + east + c.n + c.s + c.b + c.t - 6.f * c.c;
        float4 ax = 0.5f * (east - west), ay = 0.5f * (c.n - c.s), az = 0.5f * (c.t - c.b);
        st4(W1, cb, (wc + dt*(lap - buc*ax - bvc*ay - bwc*az) - dt*gpz) * fc);
    }
}

// ---------------------------------------------------------------------------
// Shared tail: c64buf -> Rp2 store + 16^3 split partial into Rp3.
// ---------------------------------------------------------------------------
static __device__ __forceinline__ void resid_tail(
    float c64buf[2][4][64], float c32buf[64],
    float* __restrict__ Rp2, float* __restrict__ Rp3, int tid)
{
    if (tid < 64) {
        int wc2 = tid & 31, hc2 = tid >> 5;
        float s = 0.f;
        #pragma unroll
        for (int dc = 0; dc < 2; ++dc)
            #pragma unroll
            for (int hh = 0; hh < 2; ++hh)
                s += c64buf[dc][hc2 * 2 + hh][wc2 * 2] + c64buf[dc][hc2 * 2 + hh][wc2 * 2 + 1];
        float v = 0.125f * s;
        c32buf[hc2 * 32 + wc2] = v;
        Rp2[((blockIdx.z) * 32 + (blockIdx.y << 1) + hc2) * 32 + wc2] = v;
    }
    __syncthreads();
    if (tid < 16) {
        float s = c32buf[tid * 2] + c32buf[tid * 2 + 1]
                + c32buf[32 + tid * 2] + c32buf[32 + tid * 2 + 1];
        int idx = (((int)blockIdx.z >> 1) * 16 + (int)blockIdx.y) * 16 + tid;
        Rp3[(blockIdx.z & 1) * 4096 + idx] = 0.125f * s;
    }
}

// ---------------------------------------------------------------------------
// Iter-0 fused: div + residual + Ppre(=p - r0/diag) + restrictions.
// ---------------------------------------------------------------------------
__global__ void __launch_bounds__(256) k_residdiv(
    const float* __restrict__ P, const float* __restrict__ U1,
    const float* __restrict__ V1, const float* __restrict__ W1,
    const float* __restrict__ DT,
    float* __restrict__ B, float* __restrict__ PP,
    float* __restrict__ Rp1, float* __restrict__ Rp2, float* __restrict__ Rp3)
{
    __shared__ float sred[8][64];
    __shared__ float c64buf[2][4][64];
    __shared__ float c32buf[64];
    const int w4 = threadIdx.x << 2;
    const int h  = (blockIdx.y << 3) + threadIdx.y;
    const int hS = cl(h - 1), hN = cl(h + 1);
    const int tid = threadIdx.y * 32 + threadIdx.x;
    const float dt = DT[0];
    const float rdt = -1.f / dt;

    #pragma unroll
    for (int pair = 0; pair < 2; ++pair) {
        S7 pp[2]; float4 u1c[2], vn[2], vs[2], wb[2], wt[2];
        float uwl[2], uwr[2]; int cbs[2];
        #pragma unroll
        for (int d2 = 0; d2 < 2; ++d2) {
            IDX6((blockIdx.z << 2) + (pair << 1) + d2);
            cbs[d2] = cb;
            pp[d2]  = ld7(P, cb, nb, sb, bb, tb, w4);
            u1c[d2] = ld4(U1, cb);
            uwl[d2] = (w4 > 0)   ? U1[cb - 1] : u1c[d2].x;
            uwr[d2] = (w4 < 124) ? U1[cb + 4] : u1c[d2].w;
            vn[d2] = ld4(V1, nb); vs[d2] = ld4(V1, sb);
            wt[d2] = ld4(W1, tb); wb[d2] = ld4(W1, bb);
        }
        float acc0 = 0.f, acc1 = 0.f;
        #pragma unroll
        for (int d2 = 0; d2 < 2; ++d2) {
            float wl = uwl[d2]; if (w4 == 0) wl = 1.0f;
            float4 west = make_float4(wl, u1c[d2].x, u1c[d2].y, u1c[d2].z);
            float4 east = make_float4(u1c[d2].y, u1c[d2].z, u1c[d2].w, uwr[d2]);
            float4 b4 = rdt * (0.5f*(east - west) + 0.5f*(vn[d2] - vs[d2]) + 0.5f*(wt[d2] - wb[d2]));
            st4(B, cbs[d2], b4);

            float4 pw = westv(pp[d2]), pe = eastv(pp[d2]);
            float4 lap = pw + pe + pp[d2].n + pp[d2].s + pp[d2].b + pp[d2].t - 6.f * pp[d2].c;
            float4 rr = lap - b4;
            st4(PP, cbs[d2], pp[d2].c - make_float4(rr.x/(-6.f), rr.y/(-6.f), rr.z/(-6.f), rr.w/(-6.f)));
            acc0 += rr.x + rr.y;
            acc1 += rr.z + rr.w;
        }
        sred[threadIdx.y][threadIdx.x * 2]     = acc0;
        sred[threadIdx.y][threadIdx.x * 2 + 1] = acc1;
        __syncthreads();
        {
            int cw = tid & 63, chh = tid >> 6;
            float v = 0.125f * (sred[2 * chh][cw] + sred[2 * chh + 1][cw]);
            int dc = (blockIdx.z << 1) + pair, hc = (blockIdx.y << 2) + chh;
            Rp1[(dc * 64 + hc) * 64 + cw] = v;
            c64buf[pair][chh][cw] = v;
        }
        __syncthreads();
    }
    resid_tail(c64buf, c32buf, Rp2, Rp3, tid);
}

// ---------------------------------------------------------------------------
// Iter-1 residual: Ppre = p - (lap(p)-B)/diag, + restrictions.
// ---------------------------------------------------------------------------
__global__ void __launch_bounds__(256) k_resid(
    const float* __restrict__ P, const float* __restrict__ B,
    float* __restrict__ PP, float* __restrict__ Rp1,
    float* __restrict__ Rp2, float* __restrict__ Rp3)
{
    __shared__ float sred[8][64];
    __shared__ float c64buf[2][4][64];
    __shared__ float c32buf[64];
    const int w4 = threadIdx.x << 2;
    const int h  = (blockIdx.y << 3) + threadIdx.y;
    const int hS = cl(h - 1), hN = cl(h + 1);
    const int tid = threadIdx.y * 32 + threadIdx.x;

    #pragma unroll
    for (int pair = 0; pair < 2; ++pair) {
        S7 pp[2]; float4 bc[2]; int cbs[2];
        #pragma unroll
        for (int d2 = 0; d2 < 2; ++d2) {
            IDX6((blockIdx.z << 2) + (pair << 1) + d2);
            cbs[d2] = cb;
            pp[d2] = ld7(P, cb, nb, sb, bb, tb, w4);
            bc[d2] = ld4(B, cb);
        }
        float acc0 = 0.f, acc1 = 0.f;
        #pragma unroll
        for (int d2 = 0; d2 < 2; ++d2) {
            float4 pw = westv(pp[d2]), pe = eastv(pp[d2]);
            float4 lap = pw + pe + pp[d2].n + pp[d2].s + pp[d2].b + pp[d2].t - 6.f * pp[d2].c;
            float4 rr = lap - bc[d2];
            st4(PP, cbs[d2], pp[d2].c - make_float4(rr.x/(-6.f), rr.y/(-6.f), rr.z/(-6.f), rr.w/(-6.f)));
            acc0 += rr.x + rr.y;
            acc1 += rr.z + rr.w;
        }
        sred[threadIdx.y][threadIdx.x * 2]     = acc0;
        sred[threadIdx.y][threadIdx.x * 2 + 1] = acc1;
        __syncthreads();
        {
            int cw = tid & 63, chh = tid >> 6;
            float v = 0.125f * (sred[2 * chh][cw] + sred[2 * chh + 1][cw]);
            int dc = (blockIdx.z << 1) + pair, hc = (blockIdx.y << 2) + chh;
            Rp1[(dc * 64 + hc) * 64 + cw] = v;
            c64buf[pair][chh][cw] = v;
        }
        __syncthreads();
    }
    resid_tail(c64buf, c32buf, Rp2, Rp3, tid);
}

static __device__ __forceinline__ float mgcell(const float* __restrict__ Wp, int mc,
                                               float r, int d, int h, int w, int m)
{
    auto g = [&](int dd, int hh, int ww) -> float {
        if (dd < 0 || dd >= m || hh < 0 || hh >= m || ww < 0 || ww >= m) return 0.f;
        return Wp[((dd >> 1) * mc + (hh >> 1)) * mc + (ww >> 1)];
    };
    float wc = g(d, h, w);
    float lap = g(d-1,h,w) + g(d+1,h,w) + g(d,h-1,w) + g(d,h+1,w) + g(d,h,w-1) + g(d,h,w+1) - 6.f * wc;
    return wc - lap / (-6.f) + r / (-6.f);
}

// padded-coarse read: fine index in [-1, m] maps to ((f>>1)+1)
static __device__ __forceinline__ float gpad(const float* __restrict__ W, int p1, int p2,
                                             int dd, int hh, int ww)
{
    return W[((dd >> 1) + 1) * p1 + ((hh >> 1) + 1) * p2 + ((ww >> 1) + 1)];
}
static __device__ __forceinline__ float mgpad(const float* __restrict__ W, int p1, int p2,
                                              float r, int d, int h, int w)
{
    float wc = gpad(W, p1, p2, d, h, w);
    float lap = gpad(W, p1, p2, d-1, h, w) + gpad(W, p1, p2, d+1, h, w)
              + gpad(W, p1, p2, d, h-1, w) + gpad(W, p1, p2, d, h+1, w)
              + gpad(W, p1, p2, d, h, w-1) + gpad(W, p1, p2, d, h, w+1) - 6.f * wc;
    return wc - lap / (-6.f) + r / (-6.f);
}

// ---------------------------------------------------------------------------
// Fused coarse MG: 128 blocks x 256 thr. EVERY block redundantly computes the
// full coarse pyramid (R16..R1, W1..W16p) in its own smem (~80K flops), then
// emits its own 256 W32 cells. Removes the serial single-block kernel + the
// separate mg32 launch. Block 0 writes o_r.
// ---------------------------------------------------------------------------
__global__ void __launch_bounds__(256) k_mgfused(
    const float* __restrict__ Rp3, const float* __restrict__ Rp2,
    float* __restrict__ W32, float* __restrict__ o_r)
{
    __shared__ float R16[4096], R8[512], R4[64], R2[8];
    __shared__ float W1p[27], W2p[64], W4p[216], W8p[1000], W16p[5832];
    const int tid = threadIdx.x;

    // zero the padded arrays
    for (int k = tid; k < 5832; k += 256) W16p[k] = 0.f;
    for (int k = tid; k < 1000; k += 256) W8p[k] = 0.f;
    if (tid < 216) W4p[tid] = 0.f;
    if (tid < 64)  W2p[tid] = 0.f;
    if (tid < 27)  W1p[tid] = 0.f;

    // R16 = Rp3[0] + Rp3[1]  (float4, 4 iters/thread)
    for (int i = tid; i < 1024; i += 256) {
        float4 a = ld4(Rp3, i << 2);
        float4 b = ld4(Rp3, 4096 + (i << 2));
        *reinterpret_cast<float4*>(R16 + (i << 2)) = a + b;
    }
    __syncthreads();
    for (int k = tid; k < 512; k += 256) {   // 16 -> 8
        int w = k & 7, h = (k >> 3) & 7, d = k >> 6;
        int b0 = ((2 * d) * 16 + 2 * h) * 16 + 2 * w;
        R8[k] = 0.125f * (R16[b0] + R16[b0+1] + R16[b0+16] + R16[b0+17]
                        + R16[b0+256] + R16[b0+257] + R16[b0+272] + R16[b0+273]);
    }
    __syncthreads();
    if (tid < 64) {    // 8 -> 4
        int w = tid & 3, h = (tid >> 2) & 3, d = tid >> 4;
        int b0 = ((2 * d) * 8 + 2 * h) * 8 + 2 * w;
        R4[tid] = 0.125f * (R8[b0] + R8[b0+1] + R8[b0+8] + R8[b0+9]
                          + R8[b0+64] + R8[b0+65] + R8[b0+72] + R8[b0+73]);
    }
    __syncthreads();
    if (tid < 8) {     // 4 -> 2
        int w = tid & 1, h = (tid >> 1) & 1, d = tid >> 2;
        int b0 = ((2 * d) * 4 + 2 * h) * 4 + 2 * w;
        R2[tid] = 0.125f * (R4[b0] + R4[b0+1] + R4[b0+4] + R4[b0+5]
                          + R4[b0+16] + R4[b0+17] + R4[b0+20] + R4[b0+21]);
    }
    __syncthreads();
    if (tid == 0) {    // 2 -> 1 + coarsest solve
        float r1 = 0.125f * (R2[0]+R2[1]+R2[2]+R2[3]+R2[4]+R2[5]+R2[6]+R2[7]);
        W1p[13] = r1 / (-6.f);
        if (o_r && blockIdx.x == 0) o_r[0] = r1;
    }
    __syncthreads();
    if (tid < 8) {     // m = 2
        int w = tid & 1, h = (tid >> 1) & 1, d = tid >> 2;
        W2p[(d+1)*16 + (h+1)*4 + (w+1)] = mgpad(W1p, 9, 3, R2[tid], d, h, w);
    }
    __syncthreads();
    if (tid < 64) {    // m = 4
        int w = tid & 3, h = (tid >> 2) & 3, d = tid >> 4;
        W4p[(d+1)*36 + (h+1)*6 + (w+1)] = mgpad(W2p, 16, 4, R4[tid], d, h, w);
    }
    __syncthreads();
    for (int k = tid; k < 512; k += 256) {   // m = 8
        int w = k & 7, h = (k >> 3) & 7, d = k >> 6;
        W8p[(d+1)*100 + (h+1)*10 + (w+1)] = mgpad(W4p, 36, 6, R8[k], d, h, w);
    }
    __syncthreads();
    for (int k = tid; k < 4096; k += 256) {  // m = 16 (padded)
        int w = k & 15, h = (k >> 4) & 15, d = k >> 8;
        W16p[(d+1)*324 + (h+1)*18 + (w+1)] = mgpad(W8p, 100, 10, R16[k], d, h, w);
    }
    __syncthreads();
    {   // m = 32: this block's own 256 cells
        const int t = blockIdx.x * 256 + tid;
        const int w = t & 31, h = (t >> 5) & 31, d = t >> 10;
        W32[t] = mgpad(W16p, 324, 18, Rp2[t], d, h, w);
    }
}

// ---------------------------------------------------------------------------
// In-place p-update with m=64 MG level fused: Pio -= mg64(W32, Rp1)
// ---------------------------------------------------------------------------
__global__ void __launch_bounds__(256) k_pupdate(
    float* __restrict__ Pio, const float* __restrict__ W32,
    const float* __restrict__ Rp1, float* __restrict__ wmg_out)
{
    const int w4 = threadIdx.x << 2;
    const int h  = (blockIdx.y << 3) + threadIdx.y;
    const int d  = blockIdx.z;
    const int cb = ix(d, h, w4);

    const int d64 = d >> 1, h64 = h >> 1, cw0 = w4 >> 1;
    const int crow = (d64 * 64 + h64) * 64 + cw0;
    const float r64_0 = Rp1[crow], r64_1 = Rp1[crow + 1];
    const float4 po = ld4(Pio, cb);

    const float mg0 = mgcell(W32, 32, r64_0, d64, h64, cw0,     64);
    const float mg1 = mgcell(W32, 32, r64_1, d64, h64, cw0 + 1, 64);
    const float4 wv = make_float4(mg0, mg0, mg1, mg1);
    st4(Pio, cb, po - wv);
    if (wmg_out) st4(wmg_out, cb, wv);
}

// ---------------------------------------------------------------------------
__global__ void __launch_bounds__(256) k_final(
    const float* __restrict__ U1, const float* __restrict__ V1, const float* __restrict__ W1,
    const float* __restrict__ Pf, const float* __restrict__ SG, const float* __restrict__ DT,
    float* __restrict__ OU, float* __restrict__ OV, float* __restrict__ OW)
{
    const int w4 = threadIdx.x << 2;
    const int h  = (blockIdx.y << 3) + threadIdx.y;
    const int hS = cl(h - 1), hN = cl(h + 1);
    IDX6(blockIdx.z);

    S7 p = ld7(Pf, cb, nb, sb, bb, tb, w4);
    const float4 sg = ld4(SG, cb);
    const float4 u1 = ld4(U1, cb), v1 = ld4(V1, cb), w1 = ld4(W1, cb);
    const float dt = DT[0];

    const float4 fc = rcp4(dt, sg);
    float4 gpx = 0.5f * (eastv(p) - westv(p));
    float4 gpy = 0.5f * (p.n - p.s);
    float4 gpz = 0.5f * (p.t - p.b);
    st4(OU, cb, (u1 - dt * gpx) * fc);
    st4(OV, cb, (v1 - dt * gpy) * fc);
    st4(OW, cb, (w1 - dt * gpz) * fc);
}

// ---------------------------------------------------------------------------
extern "C" void kernel_launch(void* const* d_in, const int* in_sizes, int n_in,
                              void* d_out, int out_size)
{
    const float* U  = (const float*)d_in[0];
    const float* V  = (const float*)d_in[1];
    const float* W_ = (const float*)d_in[2];
    const float* P  = (const float*)d_in[3];
    const float* SG = (const float*)d_in[4];
    const float* DT = (const float*)d_in[5];

    float* out   = (float*)d_out;
    float* o_u   = out;
    float* o_v   = out + (size_t)N3;
    float* o_w   = out + 2 * (size_t)N3;
    float* o_p   = out + 3 * (size_t)N3;
    float* o_wmg = out + 4 * (size_t)N3;
    float* o_r   = out + 5 * (size_t)N3;

    float* S = nullptr;
    cudaGetSymbolAddress((void**)&S, g_scratch);
    float* BU = S;
    float* BV = S + (size_t)N3;
    float* BW = S + 2 * (size_t)N3;
    float* U1 = S + 3 * (size_t)N3;
    float* V1 = S + 4 * (size_t)N3;
    float* W1 = S + 5 * (size_t)N3;
    float* B  = S + 6 * (size_t)N3;
    float* P1 = S + 7 * (size_t)N3;
    float* Rp1 = S + 8 * (size_t)N3;     // 64^3
    float* Rp2 = Rp1 + 262144;           // 32^3
    float* W32 = Rp2 + 32768;            // 32^3
    float* Rp3 = W32 + 32768;            // 2 x 16^3 split partials

    dim3 blkF(32, 4), grdF(1, 32, 128);     // fat kernels, 128 thr
    dim3 blkR(32, 8), grdR(1, 16, 32);      // residual (4 planes/block)
    dim3 grdP(1, 16, 128);                  // full-depth grids with blkR

    k_predictor<<<grdF, blkF>>>(U, V, W_, P, SG, DT, BU, BV, BW);
    k_corrector<<<grdF, blkF>>>(BU, BV, BW, U, V, W_, P, SG, DT, U1, V1, W1);

    // iteration 0: Ppre -> P1, then P1 -= wmg (in place)
    k_residdiv<<<grdR, blkR>>>(P, U1, V1, W1, DT, B, P1, Rp1, Rp2, Rp3);
    k_mgfused<<<128, 256>>>(Rp3, Rp2, W32, nullptr);
    k_pupdate<<<grdP, blkR>>>(P1, W32, Rp1, nullptr);

    // iteration 1: Ppre -> o_p, then o_p -= wmg (in place) + o_wmg
    k_resid<<<grdR, blkR>>>(P1, B, o_p, Rp1, Rp2, Rp3);
    k_mgfused<<<128, 256>>>(Rp3, Rp2, W32, o_r);
    k_pupdate<<<grdP, blkR>>>(o_p, W32, Rp1, o_wmg);

    k_final<<<grdP, blkR>>>(U1, V1, W1, o_p, SG, DT, o_u, o_v, o_w);
}

// round 16
// speedup vs baseline: 1.4160x; 1.4160x over previous
#include <cuda_runtime.h>

#define N   128
#define N3  (N*N*N)

// BU BV BW U1 V1 W1 B P1 P2 (9 x N3) + Rp1(64^3) + Rp2(32^3) + W32(32^3) + W16(16^3) + Rp3(2x16^3) + W64(64^3)
__device__ float g_scratch[9 * (size_t)N3 + 262144 + 2 * 32768 + 4096 + 8192 + 262144];

static __device__ __forceinline__ int cl(int x) { return x < 0 ? 0 : (x > N - 1 ? N - 1 : x); }
static __device__ __forceinline__ int ix(int d, int h, int w) { return (d << 14) + (h << 7) + w; }

static __device__ __forceinline__ float4 ld4(const float* __restrict__ p, int i) {
    return *reinterpret_cast<const float4*>(p + i);
}
static __device__ __forceinline__ void st4(float* __restrict__ p, int i, float4 v) {
    *reinterpret_cast<float4*>(p + i) = v;
}
static __device__ __forceinline__ float4 operator+(float4 a, float4 b) { return make_float4(a.x+b.x, a.y+b.y, a.z+b.z, a.w+b.w); }
static __device__ __forceinline__ float4 operator-(float4 a, float4 b) { return make_float4(a.x-b.x, a.y-b.y, a.z-b.z, a.w-b.w); }
static __device__ __forceinline__ float4 operator*(float s, float4 a) { return make_float4(s*a.x, s*a.y, s*a.z, s*a.w); }
static __device__ __forceinline__ float4 operator*(float4 a, float4 b) { return make_float4(a.x*b.x, a.y*b.y, a.z*b.z, a.w*b.w); }

struct S7 { float4 c, n, s, b, t; float wl, wr; };

static __device__ __forceinline__ S7 ld7(const float* __restrict__ A,
                                         int cb, int nb, int sb, int bb, int tb, int w4) {
    S7 r;
    r.c = ld4(A, cb); r.n = ld4(A, nb); r.s = ld4(A, sb); r.b = ld4(A, bb); r.t = ld4(A, tb);
    r.wl = (w4 > 0)   ? A[cb - 1] : r.c.x;
    r.wr = (w4 < 124) ? A[cb + 4] : r.c.w;
    return r;
}
static __device__ __forceinline__ float4 westv(const S7& s) { return make_float4(s.wl, s.c.x, s.c.y, s.c.z); }
static __device__ __forceinline__ float4 eastv(const S7& s) { return make_float4(s.c.y, s.c.z, s.c.w, s.wr); }

static __device__ __forceinline__ float4 rcp4(float dt, float4 g) {
    return make_float4(1.f/(1.f+dt*g.x), 1.f/(1.f+dt*g.y), 1.f/(1.f+dt*g.z), 1.f/(1.f+dt*g.w));
}
static __device__ __forceinline__ void scale7(S7& u, const S7& f) {
    u.c = u.c * f.c; u.n = u.n * f.n; u.s = u.s * f.s; u.b = u.b * f.b; u.t = u.t * f.t;
    u.wl *= f.wl; u.wr *= f.wr;
}

#define IDX6(dd)                                      \
    const int d = (dd);                               \
    const int dB = cl(d - 1), dT = cl(d + 1);         \
    const int cb = ix(d, h, w4);                      \
    const int nb = ix(d, hN, w4), sb = ix(d, hS, w4); \
    const int bb = ix(dB, h, w4), tb = ix(dT, h, w4);

// subtract the piecewise-constant W64 field from every point of a p-stencil
static __device__ __forceinline__ void sub_w64(
    S7& p, const float* __restrict__ W64,
    int d, int dB, int dT, int h, int hS, int hN, int w4, float4* wmgc_out)
{
    const int cd = d >> 1, ch = h >> 1;
    const int chN = hN >> 1, chS = hS >> 1, cdB = dB >> 1, cdT = dT >> 1;
    const int cw0 = w4 >> 1, cw1 = cw0 + 1;
    const int cwW = (w4 > 0) ? ((w4 - 1) >> 1) : 0;
    const int cwE = ((w4 < 124) ? (w4 + 4) : 127) >> 1;
    #define WG(dd, hh, ww) W64[(((dd) << 6) + (hh)) * 64 + (ww)]
    const float c0 = WG(cd, ch, cw0), c1 = WG(cd, ch, cw1);
    const float4 wmgc = make_float4(c0, c0, c1, c1);
    const float n0 = WG(cd, chN, cw0), n1 = WG(cd, chN, cw1);
    const float s0 = WG(cd, chS, cw0), s1 = WG(cd, chS, cw1);
    const float b0 = WG(cdB, ch, cw0), b1 = WG(cdB, ch, cw1);
    const float t0 = WG(cdT, ch, cw0), t1 = WG(cdT, ch, cw1);
    p.c = p.c - wmgc;
    p.n = p.n - make_float4(n0, n0, n1, n1);
    p.s = p.s - make_float4(s0, s0, s1, s1);
    p.b = p.b - make_float4(b0, b0, b1, b1);
    p.t = p.t - make_float4(t0, t0, t1, t1);
    p.wl -= WG(cd, ch, cwW);
    p.wr -= WG(cd, ch, cwE);
    #undef WG
    *wmgc_out = wmgc;
}

// ---------------------------------------------------------------------------
__global__ void __launch_bounds__(128) k_predictor(
    const float* __restrict__ U, const float* __restrict__ V, const float* __restrict__ W_,
    const float* __restrict__ P, const float* __restrict__ SG, const float* __restrict__ DT,
    float* __restrict__ BU, float* __restrict__ BV, float* __restrict__ BW)
{
    const int w4 = threadIdx.x << 2;
    const int h  = (blockIdx.y << 2) + threadIdx.y;
    const int hS = cl(h - 1), hN = cl(h + 1);
    IDX6(blockIdx.z);

    S7 g  = ld7(SG, cb, nb, sb, bb, tb, w4);
    S7 p  = ld7(P,  cb, nb, sb, bb, tb, w4);
    S7 su = ld7(U,  cb, nb, sb, bb, tb, w4);
    S7 sv = ld7(V,  cb, nb, sb, bb, tb, w4);
    S7 sw = ld7(W_, cb, nb, sb, bb, tb, w4);
    const float dt = DT[0];

    S7 f;
    f.c = rcp4(dt, g.c); f.n = rcp4(dt, g.n); f.s = rcp4(dt, g.s);
    f.b = rcp4(dt, g.b); f.t = rcp4(dt, g.t);
    f.wl = 1.f/(1.f+dt*g.wl); f.wr = 1.f/(1.f+dt*g.wr);

    scale7(su, f); scale7(sv, f); scale7(sw, f);
    const float4 uc = su.c, vc = sv.c, wc = sw.c;

    float4 gpx = 0.5f * (eastv(p) - westv(p));
    float4 gpy = 0.5f * (p.n - p.s);
    float4 gpz = 0.5f * (p.t - p.b);

    {
        float4 west = westv(su); if (w4 == 0) west.x = 1.0f;
        float4 east = eastv(su);
        float4 lap = west + east + su.n + su.s + su.b + su.t - 6.f * su.c;
        float4 ax = 0.5f * (east - west), ay = 0.5f * (su.n - su.s), az = 0.5f * (su.t - su.b);
        st4(BU, cb, (uc + 0.5f*dt*(lap - uc*ax - vc*ay - wc*az) - dt*gpx) * f.c);
    }
    {
        float4 west = westv(sv), east = eastv(sv);
        float4 lap = west + east + sv.n + sv.s + sv.b + sv.t - 6.f * sv.c;
        float4 ax = 0.5f * (east - west), ay = 0.5f * (sv.n - sv.s), az = 0.5f * (sv.t - sv.b);
        st4(BV, cb, (vc + 0.5f*dt*(lap - uc*ax - vc*ay - wc*az) - dt*gpy) * f.c);
    }
    {
        float4 west = westv(sw), east = eastv(sw);
        float4 lap = west + east + sw.n + sw.s + sw.b + sw.t - 6.f * sw.c;
        float4 ax = 0.5f * (east - west), ay = 0.5f * (sw.n - sw.s), az = 0.5f * (sw.t - sw.b);
        st4(BW, cb, (wc + 0.5f*dt*(lap - uc*ax - vc*ay - wc*az) - dt*gpz) * f.c);
    }
}

// ---------------------------------------------------------------------------
__global__ void __launch_bounds__(128) k_corrector(
    const float* __restrict__ BU, const float* __restrict__ BV, const float* __restrict__ BW,
    const float* __restrict__ U, const float* __restrict__ V, const float* __restrict__ W_,
    const float* __restrict__ P, const float* __restrict__ SG, const float* __restrict__ DT,
    float* __restrict__ U1, float* __restrict__ V1, float* __restrict__ W1)
{
    const int w4 = threadIdx.x << 2;
    const int h  = (blockIdx.y << 2) + threadIdx.y;
    const int hS = cl(h - 1), hN = cl(h + 1);
    IDX6(blockIdx.z);

    const float4 sg = ld4(SG, cb);
    const float4 Uc = ld4(U, cb), Vc = ld4(V, cb), Wc = ld4(W_, cb);
    S7 p = ld7(P,  cb, nb, sb, bb, tb, w4);
    S7 a = ld7(BU, cb, nb, sb, bb, tb, w4);
    S7 b = ld7(BV, cb, nb, sb, bb, tb, w4);
    S7 c = ld7(BW, cb, nb, sb, bb, tb, w4);
    const float dt = DT[0];

    const float4 fc = rcp4(dt, sg);
    const float4 uc = Uc * fc, vc = Vc * fc, wc = Wc * fc;
    const float4 buc = a.c, bvc = b.c, bwc = c.c;

    float4 gpx = 0.5f * (eastv(p) - westv(p));
    float4 gpy = 0.5f * (p.n - p.s);
    float4 gpz = 0.5f * (p.t - p.b);

    {
        float4 west = westv(a); if (w4 == 0) west.x = 1.0f;
        float4 east = eastv(a);
        float4 lap = west + east + a.n + a.s + a.b + a.t - 6.f * a.c;
        float4 ax = 0.5f * (east - west), ay = 0.5f * (a.n - a.s), az = 0.5f * (a.t - a.b);
        st4(U1, cb, (uc + dt*(lap - buc*ax - bvc*ay - bwc*az) - dt*gpx) * fc);
    }
    {
        float4 west = westv(b), east = eastv(b);
        float4 lap = west + east + b.n + b.s + b.b + b.t - 6.f * b.c;
        float4 ax = 0.5f * (east - west), ay = 0.5f * (b.n - b.s), az = 0.5f * (b.t - b.b);
        st4(V1, cb, (vc + dt*(lap - buc*ax - bvc*ay - bwc*az) - dt*gpy) * fc);
    }
    {
        float4 west = westv(c), east = eastv(c);
        float4 lap = west + east + c.n + c.s + c.b + c.t - 6.f * c.c;
        float4 ax = 0.5f * (east - west), ay = 0.5f * (c.n - c.s), az = 0.5f * (c.t - c.b);
        st4(W1, cb, (wc + dt*(lap - buc*ax - bvc*ay - bwc*az) - dt*gpz) * fc);
    }
}

// ---------------------------------------------------------------------------
// Shared tail: c64buf -> Rp2 store + 16^3 split partial into Rp3.
// ---------------------------------------------------------------------------
static __device__ __forceinline__ void resid_tail(
    float c64buf[2][4][64], float c32buf[64],
    float* __restrict__ Rp2, float* __restrict__ Rp3, int tid)
{
    if (tid < 64) {
        int wc2 = tid & 31, hc2 = tid >> 5;
        float s = 0.f;
        #pragma unroll
        for (int dc = 0; dc < 2; ++dc)
            #pragma unroll
            for (int hh = 0; hh < 2; ++hh)
                s += c64buf[dc][hc2 * 2 + hh][wc2 * 2] + c64buf[dc][hc2 * 2 + hh][wc2 * 2 + 1];
        float v = 0.125f * s;
        c32buf[hc2 * 32 + wc2] = v;
        Rp2[((blockIdx.z) * 32 + (blockIdx.y << 1) + hc2) * 32 + wc2] = v;
    }
    __syncthreads();
    if (tid < 16) {
        float s = c32buf[tid * 2] + c32buf[tid * 2 + 1]
                + c32buf[32 + tid * 2] + c32buf[32 + tid * 2 + 1];
        int idx = (((int)blockIdx.z >> 1) * 16 + (int)blockIdx.y) * 16 + tid;
        Rp3[(blockIdx.z & 1) * 4096 + idx] = 0.125f * s;
    }
}

// ---------------------------------------------------------------------------
// Iter-0 fused: div + residual + Ppre0(=p - r0/diag) + restrictions.
// ---------------------------------------------------------------------------
__global__ void __launch_bounds__(256) k_residdiv(
    const float* __restrict__ P, const float* __restrict__ U1,
    const float* __restrict__ V1, const float* __restrict__ W1,
    const float* __restrict__ DT,
    float* __restrict__ B, float* __restrict__ PP,
    float* __restrict__ Rp1, float* __restrict__ Rp2, float* __restrict__ Rp3)
{
    __shared__ float sred[8][64];
    __shared__ float c64buf[2][4][64];
    __shared__ float c32buf[64];
    const int w4 = threadIdx.x << 2;
    const int h  = (blockIdx.y << 3) + threadIdx.y;
    const int hS = cl(h - 1), hN = cl(h + 1);
    const int tid = threadIdx.y * 32 + threadIdx.x;
    const float dt = DT[0];
    const float rdt = -1.f / dt;

    #pragma unroll
    for (int pair = 0; pair < 2; ++pair) {
        S7 pp[2]; float4 u1c[2], vn[2], vs[2], wb[2], wt[2];
        float uwl[2], uwr[2]; int cbs[2];
        #pragma unroll
        for (int d2 = 0; d2 < 2; ++d2) {
            IDX6((blockIdx.z << 2) + (pair << 1) + d2);
            cbs[d2] = cb;
            pp[d2]  = ld7(P, cb, nb, sb, bb, tb, w4);
            u1c[d2] = ld4(U1, cb);
            uwl[d2] = (w4 > 0)   ? U1[cb - 1] : u1c[d2].x;
            uwr[d2] = (w4 < 124) ? U1[cb + 4] : u1c[d2].w;
            vn[d2] = ld4(V1, nb); vs[d2] = ld4(V1, sb);
            wt[d2] = ld4(W1, tb); wb[d2] = ld4(W1, bb);
        }
        float acc0 = 0.f, acc1 = 0.f;
        #pragma unroll
        for (int d2 = 0; d2 < 2; ++d2) {
            float wl = uwl[d2]; if (w4 == 0) wl = 1.0f;
            float4 west = make_float4(wl, u1c[d2].x, u1c[d2].y, u1c[d2].z);
            float4 east = make_float4(u1c[d2].y, u1c[d2].z, u1c[d2].w, uwr[d2]);
            float4 b4 = rdt * (0.5f*(east - west) + 0.5f*(vn[d2] - vs[d2]) + 0.5f*(wt[d2] - wb[d2]));
            st4(B, cbs[d2], b4);

            float4 pw = westv(pp[d2]), pe = eastv(pp[d2]);
            float4 lap = pw + pe + pp[d2].n + pp[d2].s + pp[d2].b + pp[d2].t - 6.f * pp[d2].c;
            float4 rr = lap - b4;
            st4(PP, cbs[d2], pp[d2].c - make_float4(rr.x/(-6.f), rr.y/(-6.f), rr.z/(-6.f), rr.w/(-6.f)));
            acc0 += rr.x + rr.y;
            acc1 += rr.z + rr.w;
        }
        sred[threadIdx.y][threadIdx.x * 2]     = acc0;
        sred[threadIdx.y][threadIdx.x * 2 + 1] = acc1;
        __syncthreads();
        {
            int cw = tid & 63, chh = tid >> 6;
            float v = 0.125f * (sred[2 * chh][cw] + sred[2 * chh + 1][cw]);
            int dc = (blockIdx.z << 1) + pair, hc = (blockIdx.y << 2) + chh;
            Rp1[(dc * 64 + hc) * 64 + cw] = v;
            c64buf[pair][chh][cw] = v;
        }
        __syncthreads();
    }
    resid_tail(c64buf, c32buf, Rp2, Rp3, tid);
}

// ---------------------------------------------------------------------------
// Iter-1 residual with iter-0 p-update fused:
// p1 = Ppre0 - W64_0[x>>1]; r1 = lap(p1) - B; Ppre1 = p1 - r1/diag -> PP1.
// ---------------------------------------------------------------------------
__global__ void __launch_bounds__(256) k_resid2(
    const float* __restrict__ PP0, const float* __restrict__ B,
    const float* __restrict__ W64,
    float* __restrict__ PP1, float* __restrict__ Rp1,
    float* __restrict__ Rp2, float* __restrict__ Rp3)
{
    __shared__ float sred[8][64];
    __shared__ float c64buf[2][4][64];
    __shared__ float c32buf[64];
    const int w4 = threadIdx.x << 2;
    const int h  = (blockIdx.y << 3) + threadIdx.y;
    const int hS = cl(h - 1), hN = cl(h + 1);
    const int tid = threadIdx.y * 32 + threadIdx.x;

    #pragma unroll
    for (int pair = 0; pair < 2; ++pair) {
        S7 pp[2]; float4 bc[2]; int cbs[2]; float4 wmgc[2];
        #pragma unroll
        for (int d2 = 0; d2 < 2; ++d2) {
            IDX6((blockIdx.z << 2) + (pair << 1) + d2);
            cbs[d2] = cb;
            pp[d2] = ld7(PP0, cb, nb, sb, bb, tb, w4);
            bc[d2] = ld4(B, cb);
            sub_w64(pp[d2], W64, d, dB, dT, h, hS, hN, w4, &wmgc[d2]);
        }
        float acc0 = 0.f, acc1 = 0.f;
        #pragma unroll
        for (int d2 = 0; d2 < 2; ++d2) {
            float4 pw = westv(pp[d2]), pe = eastv(pp[d2]);
            float4 lap = pw + pe + pp[d2].n + pp[d2].s + pp[d2].b + pp[d2].t - 6.f * pp[d2].c;
            float4 rr = lap - bc[d2];
            st4(PP1, cbs[d2], pp[d2].c - make_float4(rr.x/(-6.f), rr.y/(-6.f), rr.z/(-6.f), rr.w/(-6.f)));
            acc0 += rr.x + rr.y;
            acc1 += rr.z + rr.w;
        }
        sred[threadIdx.y][threadIdx.x * 2]     = acc0;
        sred[threadIdx.y][threadIdx.x * 2 + 1] = acc1;
        __syncthreads();
        {
            int cw = tid & 63, chh = tid >> 6;
            float v = 0.125f * (sred[2 * chh][cw] + sred[2 * chh + 1][cw]);
            int dc = (blockIdx.z << 1) + pair, hc = (blockIdx.y << 2) + chh;
            Rp1[(dc * 64 + hc) * 64 + cw] = v;
            c64buf[pair][chh][cw] = v;
        }
        __syncthreads();
    }
    resid_tail(c64buf, c32buf, Rp2, Rp3, tid);
}

static __device__ __forceinline__ float mgcell(const float* __restrict__ Wp, int mc,
                                               float r, int d, int h, int w, int m)
{
    auto g = [&](int dd, int hh, int ww) -> float {
        if (dd < 0 || dd >= m || hh < 0 || hh >= m || ww < 0 || ww >= m) return 0.f;
        return Wp[((dd >> 1) * mc + (hh >> 1)) * mc + (ww >> 1)];
    };
    float wc = g(d, h, w);
    float lap = g(d-1,h,w) + g(d+1,h,w) + g(d,h-1,w) + g(d,h+1,w) + g(d,h,w-1) + g(d,h,w+1) - 6.f * wc;
    return wc - lap / (-6.f) + r / (-6.f);
}

static __device__ __forceinline__ float gpad(const float* __restrict__ W, int p1, int p2,
                                             int dd, int hh, int ww)
{
    return W[((dd >> 1) + 1) * p1 + ((hh >> 1) + 1) * p2 + ((ww >> 1) + 1)];
}
static __device__ __forceinline__ float mgpad(const float* __restrict__ W, int p1, int p2,
                                              float r, int d, int h, int w)
{
    float wc = gpad(W, p1, p2, d, h, w);
    float lap = gpad(W, p1, p2, d-1, h, w) + gpad(W, p1, p2, d+1, h, w)
              + gpad(W, p1, p2, d, h-1, w) + gpad(W, p1, p2, d, h+1, w)
              + gpad(W, p1, p2, d, h, w-1) + gpad(W, p1, p2, d, h, w+1) - 6.f * wc;
    return wc - lap / (-6.f) + r / (-6.f);
}

// ---------------------------------------------------------------------------
// Single-block coarse solver (1024 thr): R16 = Rp3[0]+Rp3[1], pyramid to 1,
// solve back up to W16. Padded smem, branch-free mgcells.
// ---------------------------------------------------------------------------
__global__ void __launch_bounds__(1024) k_coarse16(
    const float* __restrict__ Rp3, float* __restrict__ W16g, float* __restrict__ o_r)
{
    __shared__ float R16[4096], R8[512], R4[64], R2[8];
    __shared__ float W8p[1000], W4p[216], W2p[64], W1p[27];
    const int tid = threadIdx.x;

    if (tid < 1000) W8p[tid] = 0.f;
    if (tid < 216) W4p[tid] = 0.f;
    if (tid >= 256 && tid < 320) W2p[tid - 256] = 0.f;
    if (tid >= 512 && tid < 539) W1p[tid - 512] = 0.f;

    {
        const int k4 = tid << 2;
        float4 a = ld4(Rp3, k4);
        float4 b = ld4(Rp3, 4096 + k4);
        *reinterpret_cast<float4*>(R16 + k4) = a + b;
    }
    __syncthreads();
    if (tid < 512) {
        int w = tid & 7, h = (tid >> 3) & 7, d = tid >> 6;
        int b0 = ((2 * d) * 16 + 2 * h) * 16 + 2 * w;
        R8[tid] = 0.125f * (R16[b0] + R16[b0+1] + R16[b0+16] + R16[b0+17]
                          + R16[b0+256] + R16[b0+257] + R16[b0+272] + R16[b0+273]);
    }
    __syncthreads();
    if (tid < 64) {
        int w = tid & 3, h = (tid >> 2) & 3, d = tid >> 4;
        int b0 = ((2 * d) * 8 + 2 * h) * 8 + 2 * w;
        R4[tid] = 0.125f * (R8[b0] + R8[b0+1] + R8[b0+8] + R8[b0+9]
                          + R8[b0+64] + R8[b0+65] + R8[b0+72] + R8[b0+73]);
    }
    __syncthreads();
    if (tid < 8) {
        int w = tid & 1, h = (tid >> 1) & 1, d = tid >> 2;
        int b0 = ((2 * d) * 4 + 2 * h) * 4 + 2 * w;
        R2[tid] = 0.125f * (R4[b0] + R4[b0+1] + R4[b0+4] + R4[b0+5]
                          + R4[b0+16] + R4[b0+17] + R4[b0+20] + R4[b0+21]);
    }
    __syncthreads();
    if (tid == 0) {
        float r1 = 0.125f * (R2[0]+R2[1]+R2[2]+R2[3]+R2[4]+R2[5]+R2[6]+R2[7]);
        W1p[13] = r1 / (-6.f);
        if (o_r) o_r[0] = r1;
    }
    __syncthreads();
    if (tid < 8) {
        int w = tid & 1, h = (tid >> 1) & 1, d = tid >> 2;
        W2p[(d+1)*16 + (h+1)*4 + (w+1)] = mgpad(W1p, 9, 3, R2[tid], d, h, w);
    }
    __syncthreads();
    if (tid < 64) {
        int w = tid & 3, h = (tid >> 2) & 3, d = tid >> 4;
        W4p[(d+1)*36 + (h+1)*6 + (w+1)] = mgpad(W2p, 16, 4, R4[tid], d, h, w);
    }
    __syncthreads();
    if (tid < 512) {
        int w = tid & 7, h = (tid >> 3) & 7, d = tid >> 6;
        W8p[(d+1)*100 + (h+1)*10 + (w+1)] = mgpad(W4p, 36, 6, R8[tid], d, h, w);
    }
    __syncthreads();
    #pragma unroll
    for (int k = tid; k < 4096; k += 1024) {
        int w = k & 15, h = (k >> 4) & 15, d = k >> 8;
        W16g[k] = mgpad(W8p, 100, 10, R16[k], d, h, w);
    }
}

// m=32 MG level, grid-wide
__global__ void __launch_bounds__(256) k_mg32(
    const float* __restrict__ W16, const float* __restrict__ Rp2, float* __restrict__ W32)
{
    const int t = blockIdx.x * 256 + threadIdx.x;   // 32768
    const int w = t & 31, h = (t >> 5) & 31, d = t >> 10;
    W32[t] = mgcell(W16, 16, Rp2[t], d, h, w, 32);
}

// m=64 MG level materialized: W64[c] = mgcell64(W32, Rp1)
__global__ void __launch_bounds__(256) k_w64(
    const float* __restrict__ W32, const float* __restrict__ Rp1, float* __restrict__ W64)
{
    const int t = blockIdx.x * 256 + threadIdx.x;   // 262144
    const int w = t & 63, h = (t >> 6) & 63, d = t >> 12;
    W64[t] = mgcell(W32, 32, Rp1[t], d, h, w, 64);
}

// ---------------------------------------------------------------------------
// Final fused: p_final = Ppre1 - W64_1; writes o_p, o_wmg, and velocity update.
// ---------------------------------------------------------------------------
__global__ void __launch_bounds__(256) k_final2(
    const float* __restrict__ U1, const float* __restrict__ V1, const float* __restrict__ W1,
    const float* __restrict__ PP1, const float* __restrict__ W64,
    const float* __restrict__ SG, const float* __restrict__ DT,
    float* __restrict__ OU, float* __restrict__ OV, float* __restrict__ OW,
    float* __restrict__ OP, float* __restrict__ OWMG)
{
    const int w4 = threadIdx.x << 2;
    const int h  = (blockIdx.y << 3) + threadIdx.y;
    const int hS = cl(h - 1), hN = cl(h + 1);
    IDX6(blockIdx.z);

    S7 p = ld7(PP1, cb, nb, sb, bb, tb, w4);
    const float4 sg = ld4(SG, cb);
    const float4 u1 = ld4(U1, cb), v1 = ld4(V1, cb), w1 = ld4(W1, cb);
    const float dt = DT[0];

    float4 wmgc;
    sub_w64(p, W64, d, dB, dT, h, hS, hN, w4, &wmgc);

    const float4 fc = rcp4(dt, sg);
    float4 gpx = 0.5f * (eastv(p) - westv(p));
    float4 gpy = 0.5f * (p.n - p.s);
    float4 gpz = 0.5f * (p.t - p.b);
    st4(OU, cb, (u1 - dt * gpx) * fc);
    st4(OV, cb, (v1 - dt * gpy) * fc);
    st4(OW, cb, (w1 - dt * gpz) * fc);
    st4(OP, cb, p.c);
    st4(OWMG, cb, wmgc);
}

// ---------------------------------------------------------------------------
extern "C" void kernel_launch(void* const* d_in, const int* in_sizes, int n_in,
                              void* d_out, int out_size)
{
    const float* U  = (const float*)d_in[0];
    const float* V  = (const float*)d_in[1];
    const float* W_ = (const float*)d_in[2];
    const float* P  = (const float*)d_in[3];
    const float* SG = (const float*)d_in[4];
    const float* DT = (const float*)d_in[5];

    float* out   = (float*)d_out;
    float* o_u   = out;
    float* o_v   = out + (size_t)N3;
    float* o_w   = out + 2 * (size_t)N3;
    float* o_p   = out + 3 * (size_t)N3;
    float* o_wmg = out + 4 * (size_t)N3;
    float* o_r   = out + 5 * (size_t)N3;

    float* S = nullptr;
    cudaGetSymbolAddress((void**)&S, g_scratch);
    float* BU = S;
    float* BV = S + (size_t)N3;
    float* BW = S + 2 * (size_t)N3;
    float* U1 = S + 3 * (size_t)N3;
    float* V1 = S + 4 * (size_t)N3;
    float* W1 = S + 5 * (size_t)N3;
    float* B  = S + 6 * (size_t)N3;
    float* P1 = S + 7 * (size_t)N3;   // Ppre0
    float* P2 = S + 8 * (size_t)N3;   // Ppre1
    float* Rp1 = S + 9 * (size_t)N3;     // 64^3
    float* Rp2 = Rp1 + 262144;           // 32^3
    float* W32 = Rp2 + 32768;            // 32^3
    float* W16 = W32 + 32768;            // 16^3
    float* Rp3 = W16 + 4096;             // 2 x 16^3 split partials
    float* W64 = Rp3 + 8192;             // 64^3

    dim3 blkF(32, 4), grdF(1, 32, 128);     // fat kernels, 128 thr
    dim3 blkR(32, 8), grdR(1, 16, 32);      // residual (4 planes/block)
    dim3 grdP(1, 16, 128);

    k_predictor<<<grdF, blkF>>>(U, V, W_, P, SG, DT, BU, BV, BW);
    k_corrector<<<grdF, blkF>>>(BU, BV, BW, U, V, W_, P, SG, DT, U1, V1, W1);

    // iteration 0: Ppre0 -> P1; coarse chain -> W64_0
    k_residdiv<<<grdR, blkR>>>(P, U1, V1, W1, DT, B, P1, Rp1, Rp2, Rp3);
    k_coarse16<<<1, 1024>>>(Rp3, W16, nullptr);
    k_mg32<<<128, 256>>>(W16, Rp2, W32);
    k_w64<<<1024, 256>>>(W32, Rp1, W64);

    // iteration 1: p1 = Ppre0 - W64_0 reconstructed inline; Ppre1 -> P2
    k_resid2<<<grdR, blkR>>>(P1, B, W64, P2, Rp1, Rp2, Rp3);
    k_coarse16<<<1, 1024>>>(Rp3, W16, o_r);
    k_mg32<<<128, 256>>>(W16, Rp2, W32);
    k_w64<<<1024, 256>>>(W32, Rp1, W64);

    // final: p_final = Ppre1 - W64_1; velocity projection; o_p/o_wmg emitted here
    k_final2<<<grdP, blkR>>>(U1, V1, W1, P2, W64, SG, DT, o_u, o_v, o_w, o_p, o_wmg);
}

// round 17
// speedup vs baseline: 1.4298x; 1.0097x over previous
#include <cuda_runtime.h>

#define N   128
#define N3  (N*N*N)

// BU BV BW U1 V1 W1 B P1 P2 (9 x N3) + Rp1(64^3) + Rp2(32^3) + W16(16^3) + Rp3(2x16^3) + W64(64^3)
__device__ float g_scratch[9 * (size_t)N3 + 262144 + 32768 + 4096 + 8192 + 262144];

static __device__ __forceinline__ int cl(int x) { return x < 0 ? 0 : (x > N - 1 ? N - 1 : x); }
static __device__ __forceinline__ int ix(int d, int h, int w) { return (d << 14) + (h << 7) + w; }

static __device__ __forceinline__ float4 ld4(const float* __restrict__ p, int i) {
    return *reinterpret_cast<const float4*>(p + i);
}
static __device__ __forceinline__ void st4(float* __restrict__ p, int i, float4 v) {
    *reinterpret_cast<float4*>(p + i) = v;
}
static __device__ __forceinline__ float4 operator+(float4 a, float4 b) { return make_float4(a.x+b.x, a.y+b.y, a.z+b.z, a.w+b.w); }
static __device__ __forceinline__ float4 operator-(float4 a, float4 b) { return make_float4(a.x-b.x, a.y-b.y, a.z-b.z, a.w-b.w); }
static __device__ __forceinline__ float4 operator*(float s, float4 a) { return make_float4(s*a.x, s*a.y, s*a.z, s*a.w); }
static __device__ __forceinline__ float4 operator*(float4 a, float4 b) { return make_float4(a.x*b.x, a.y*b.y, a.z*b.z, a.w*b.w); }

struct S7 { float4 c, n, s, b, t; float wl, wr; };

static __device__ __forceinline__ S7 ld7(const float* __restrict__ A,
                                         int cb, int nb, int sb, int bb, int tb, int w4) {
    S7 r;
    r.c = ld4(A, cb); r.n = ld4(A, nb); r.s = ld4(A, sb); r.b = ld4(A, bb); r.t = ld4(A, tb);
    r.wl = (w4 > 0)   ? A[cb - 1] : r.c.x;
    r.wr = (w4 < 124) ? A[cb + 4] : r.c.w;
    return r;
}
static __device__ __forceinline__ float4 westv(const S7& s) { return make_float4(s.wl, s.c.x, s.c.y, s.c.z); }
static __device__ __forceinline__ float4 eastv(const S7& s) { return make_float4(s.c.y, s.c.z, s.c.w, s.wr); }

static __device__ __forceinline__ float4 rcp4(float dt, float4 g) {
    return make_float4(1.f/(1.f+dt*g.x), 1.f/(1.f+dt*g.y), 1.f/(1.f+dt*g.z), 1.f/(1.f+dt*g.w));
}
static __device__ __forceinline__ void scale7(S7& u, const S7& f) {
    u.c = u.c * f.c; u.n = u.n * f.n; u.s = u.s * f.s; u.b = u.b * f.b; u.t = u.t * f.t;
    u.wl *= f.wl; u.wr *= f.wr;
}

#define IDX6(dd)                                      \
    const int d = (dd);                               \
    const int dB = cl(d - 1), dT = cl(d + 1);         \
    const int cb = ix(d, h, w4);                      \
    const int nb = ix(d, hN, w4), sb = ix(d, hS, w4); \
    const int bb = ix(dB, h, w4), tb = ix(dT, h, w4);

// subtract the piecewise-constant W64 field from every point of a p-stencil
static __device__ __forceinline__ void sub_w64(
    S7& p, const float* __restrict__ W64,
    int d, int dB, int dT, int h, int hS, int hN, int w4, float4* wmgc_out)
{
    const int cd = d >> 1, ch = h >> 1;
    const int chN = hN >> 1, chS = hS >> 1, cdB = dB >> 1, cdT = dT >> 1;
    const int cw0 = w4 >> 1, cw1 = cw0 + 1;
    const int cwW = (w4 > 0) ? ((w4 - 1) >> 1) : 0;
    const int cwE = ((w4 < 124) ? (w4 + 4) : 127) >> 1;
    #define WG(dd, hh, ww) W64[(((dd) << 6) + (hh)) * 64 + (ww)]
    const float c0 = WG(cd, ch, cw0), c1 = WG(cd, ch, cw1);
    const float4 wmgc = make_float4(c0, c0, c1, c1);
    const float n0 = WG(cd, chN, cw0), n1 = WG(cd, chN, cw1);
    const float s0 = WG(cd, chS, cw0), s1 = WG(cd, chS, cw1);
    const float b0 = WG(cdB, ch, cw0), b1 = WG(cdB, ch, cw1);
    const float t0 = WG(cdT, ch, cw0), t1 = WG(cdT, ch, cw1);
    p.c = p.c - wmgc;
    p.n = p.n - make_float4(n0, n0, n1, n1);
    p.s = p.s - make_float4(s0, s0, s1, s1);
    p.b = p.b - make_float4(b0, b0, b1, b1);
    p.t = p.t - make_float4(t0, t0, t1, t1);
    p.wl -= WG(cd, ch, cwW);
    p.wr -= WG(cd, ch, cwE);
    #undef WG
    *wmgc_out = wmgc;
}

// ---------------------------------------------------------------------------
__global__ void __launch_bounds__(128) k_predictor(
    const float* __restrict__ U, const float* __restrict__ V, const float* __restrict__ W_,
    const float* __restrict__ P, const float* __restrict__ SG, const float* __restrict__ DT,
    float* __restrict__ BU, float* __restrict__ BV, float* __restrict__ BW)
{
    const int w4 = threadIdx.x << 2;
    const int h  = (blockIdx.y << 2) + threadIdx.y;
    const int hS = cl(h - 1), hN = cl(h + 1);
    IDX6(blockIdx.z);

    S7 g  = ld7(SG, cb, nb, sb, bb, tb, w4);
    S7 p  = ld7(P,  cb, nb, sb, bb, tb, w4);
    S7 su = ld7(U,  cb, nb, sb, bb, tb, w4);
    S7 sv = ld7(V,  cb, nb, sb, bb, tb, w4);
    S7 sw = ld7(W_, cb, nb, sb, bb, tb, w4);
    const float dt = DT[0];

    S7 f;
    f.c = rcp4(dt, g.c); f.n = rcp4(dt, g.n); f.s = rcp4(dt, g.s);
    f.b = rcp4(dt, g.b); f.t = rcp4(dt, g.t);
    f.wl = 1.f/(1.f+dt*g.wl); f.wr = 1.f/(1.f+dt*g.wr);

    scale7(su, f); scale7(sv, f); scale7(sw, f);
    const float4 uc = su.c, vc = sv.c, wc = sw.c;

    float4 gpx = 0.5f * (eastv(p) - westv(p));
    float4 gpy = 0.5f * (p.n - p.s);
    float4 gpz = 0.5f * (p.t - p.b);

    {
        float4 west = westv(su); if (w4 == 0) west.x = 1.0f;
        float4 east = eastv(su);
        float4 lap = west + east + su.n + su.s + su.b + su.t - 6.f * su.c;
        float4 ax = 0.5f * (east - west), ay = 0.5f * (su.n - su.s), az = 0.5f * (su.t - su.b);
        st4(BU, cb, (uc + 0.5f*dt*(lap - uc*ax - vc*ay - wc*az) - dt*gpx) * f.c);
    }
    {
        float4 west = westv(sv), east = eastv(sv);
        float4 lap = west + east + sv.n + sv.s + sv.b + sv.t - 6.f * sv.c;
        float4 ax = 0.5f * (east - west), ay = 0.5f * (sv.n - sv.s), az = 0.5f * (sv.t - sv.b);
        st4(BV, cb, (vc + 0.5f*dt*(lap - uc*ax - vc*ay - wc*az) - dt*gpy) * f.c);
    }
    {
        float4 west = westv(sw), east = eastv(sw);
        float4 lap = west + east + sw.n + sw.s + sw.b + sw.t - 6.f * sw.c;
        float4 ax = 0.5f * (east - west), ay = 0.5f * (sw.n - sw.s), az = 0.5f * (sw.t - sw.b);
        st4(BW, cb, (wc + 0.5f*dt*(lap - uc*ax - vc*ay - wc*az) - dt*gpz) * f.c);
    }
}

// ---------------------------------------------------------------------------
__global__ void __launch_bounds__(128) k_corrector(
    const float* __restrict__ BU, const float* __restrict__ BV, const float* __restrict__ BW,
    const float* __restrict__ U, const float* __restrict__ V, const float* __restrict__ W_,
    const float* __restrict__ P, const float* __restrict__ SG, const float* __restrict__ DT,
    float* __restrict__ U1, float* __restrict__ V1, float* __restrict__ W1)
{
    const int w4 = threadIdx.x << 2;
    const int h  = (blockIdx.y << 2) + threadIdx.y;
    const int hS = cl(h - 1), hN = cl(h + 1);
    IDX6(blockIdx.z);

    const float4 sg = ld4(SG, cb);
    const float4 Uc = ld4(U, cb), Vc = ld4(V, cb), Wc = ld4(W_, cb);
    S7 p = ld7(P,  cb, nb, sb, bb, tb, w4);
    S7 a = ld7(BU, cb, nb, sb, bb, tb, w4);
    S7 b = ld7(BV, cb, nb, sb, bb, tb, w4);
    S7 c = ld7(BW, cb, nb, sb, bb, tb, w4);
    const float dt = DT[0];

    const float4 fc = rcp4(dt, sg);
    const float4 uc = Uc * fc, vc = Vc * fc, wc = Wc * fc;
    const float4 buc = a.c, bvc = b.c, bwc = c.c;

    float4 gpx = 0.5f * (eastv(p) - westv(p));
    float4 gpy = 0.5f * (p.n - p.s);
    float4 gpz = 0.5f * (p.t - p.b);

    {
        float4 west = westv(a); if (w4 == 0) west.x = 1.0f;
        float4 east = eastv(a);
        float4 lap = west + east + a.n + a.s + a.b + a.t - 6.f * a.c;
        float4 ax = 0.5f * (east - west), ay = 0.5f * (a.n - a.s), az = 0.5f * (a.t - a.b);
        st4(U1, cb, (uc + dt*(lap - buc*ax - bvc*ay - bwc*az) - dt*gpx) * fc);
    }
    {
        float4 west = westv(b), east = eastv(b);
        float4 lap = west + east + b.n + b.s + b.b + b.t - 6.f * b.c;
        float4 ax = 0.5f * (east - west), ay = 0.5f * (b.n - b.s), az = 0.5f * (b.t - b.b);
        st4(V1, cb, (vc + dt*(lap - buc*ax - bvc*ay - bwc*az) - dt*gpy) * fc);
    }
    {
        float4 west = westv(c), east = eastv(c);
        float4 lap = west + east + c.n + c.s + c.b + c.t - 6.f * c.c;
        float4 ax = 0.5f * (east - west), ay = 0.5f * (c.n - c.s), az = 0.5f * (c.t - c.b);
        st4(W1, cb, (wc + dt*(lap - buc*ax - bvc*ay - bwc*az) - dt*gpz) * fc);
    }
}

// ---------------------------------------------------------------------------
static __device__ __forceinline__ void resid_tail(
    float c64buf[2][4][64], float c32buf[64],
    float* __restrict__ Rp2, float* __restrict__ Rp3, int tid)
{
    if (tid < 64) {
        int wc2 = tid & 31, hc2 = tid >> 5;
        float s = 0.f;
        #pragma unroll
        for (int dc = 0; dc < 2; ++dc)
            #pragma unroll
            for (int hh = 0; hh < 2; ++hh)
                s += c64buf[dc][hc2 * 2 + hh][wc2 * 2] + c64buf[dc][hc2 * 2 + hh][wc2 * 2 + 1];
        float v = 0.125f * s;
        c32buf[hc2 * 32 + wc2] = v;
        Rp2[((blockIdx.z) * 32 + (blockIdx.y << 1) + hc2) * 32 + wc2] = v;
    }
    __syncthreads();
    if (tid < 16) {
        float s = c32buf[tid * 2] + c32buf[tid * 2 + 1]
                + c32buf[32 + tid * 2] + c32buf[32 + tid * 2 + 1];
        int idx = (((int)blockIdx.z >> 1) * 16 + (int)blockIdx.y) * 16 + tid;
        Rp3[(blockIdx.z & 1) * 4096 + idx] = 0.125f * s;
    }
}

// ---------------------------------------------------------------------------
__global__ void __launch_bounds__(256) k_residdiv(
    const float* __restrict__ P, const float* __restrict__ U1,
    const float* __restrict__ V1, const float* __restrict__ W1,
    const float* __restrict__ DT,
    float* __restrict__ B, float* __restrict__ PP,
    float* __restrict__ Rp1, float* __restrict__ Rp2, float* __restrict__ Rp3)
{
    __shared__ float sred[8][64];
    __shared__ float c64buf[2][4][64];
    __shared__ float c32buf[64];
    const int w4 = threadIdx.x << 2;
    const int h  = (blockIdx.y << 3) + threadIdx.y;
    const int hS = cl(h - 1), hN = cl(h + 1);
    const int tid = threadIdx.y * 32 + threadIdx.x;
    const float dt = DT[0];
    const float rdt = -1.f / dt;

    #pragma unroll
    for (int pair = 0; pair < 2; ++pair) {
        S7 pp[2]; float4 u1c[2], vn[2], vs[2], wb[2], wt[2];
        float uwl[2], uwr[2]; int cbs[2];
        #pragma unroll
        for (int d2 = 0; d2 < 2; ++d2) {
            IDX6((blockIdx.z << 2) + (pair << 1) + d2);
            cbs[d2] = cb;
            pp[d2]  = ld7(P, cb, nb, sb, bb, tb, w4);
            u1c[d2] = ld4(U1, cb);
            uwl[d2] = (w4 > 0)   ? U1[cb - 1] : u1c[d2].x;
            uwr[d2] = (w4 < 124) ? U1[cb + 4] : u1c[d2].w;
            vn[d2] = ld4(V1, nb); vs[d2] = ld4(V1, sb);
            wt[d2] = ld4(W1, tb); wb[d2] = ld4(W1, bb);
        }
        float acc0 = 0.f, acc1 = 0.f;
        #pragma unroll
        for (int d2 = 0; d2 < 2; ++d2) {
            float wl = uwl[d2]; if (w4 == 0) wl = 1.0f;
            float4 west = make_float4(wl, u1c[d2].x, u1c[d2].y, u1c[d2].z);
            float4 east = make_float4(u1c[d2].y, u1c[d2].z, u1c[d2].w, uwr[d2]);
            float4 b4 = rdt * (0.5f*(east - west) + 0.5f*(vn[d2] - vs[d2]) + 0.5f*(wt[d2] - wb[d2]));
            st4(B, cbs[d2], b4);

            float4 pw = westv(pp[d2]), pe = eastv(pp[d2]);
            float4 lap = pw + pe + pp[d2].n + pp[d2].s + pp[d2].b + pp[d2].t - 6.f * pp[d2].c;
            float4 rr = lap - b4;
            st4(PP, cbs[d2], pp[d2].c - make_float4(rr.x/(-6.f), rr.y/(-6.f), rr.z/(-6.f), rr.w/(-6.f)));
            acc0 += rr.x + rr.y;
            acc1 += rr.z + rr.w;
        }
        sred[threadIdx.y][threadIdx.x * 2]     = acc0;
        sred[threadIdx.y][threadIdx.x * 2 + 1] = acc1;
        __syncthreads();
        {
            int cw = tid & 63, chh = tid >> 6;
            float v = 0.125f * (sred[2 * chh][cw] + sred[2 * chh + 1][cw]);
            int dc = (blockIdx.z << 1) + pair, hc = (blockIdx.y << 2) + chh;
            Rp1[(dc * 64 + hc) * 64 + cw] = v;
            c64buf[pair][chh][cw] = v;
        }
        __syncthreads();
    }
    resid_tail(c64buf, c32buf, Rp2, Rp3, tid);
}

// ---------------------------------------------------------------------------
__global__ void __launch_bounds__(256) k_resid2(
    const float* __restrict__ PP0, const float* __restrict__ B,
    const float* __restrict__ W64,
    float* __restrict__ PP1, float* __restrict__ Rp1,
    float* __restrict__ Rp2, float* __restrict__ Rp3)
{
    __shared__ float sred[8][64];
    __shared__ float c64buf[2][4][64];
    __shared__ float c32buf[64];
    const int w4 = threadIdx.x << 2;
    const int h  = (blockIdx.y << 3) + threadIdx.y;
    const int hS = cl(h - 1), hN = cl(h + 1);
    const int tid = threadIdx.y * 32 + threadIdx.x;

    #pragma unroll
    for (int pair = 0; pair < 2; ++pair) {
        S7 pp[2]; float4 bc[2]; int cbs[2]; float4 wmgc[2];
        #pragma unroll
        for (int d2 = 0; d2 < 2; ++d2) {
            IDX6((blockIdx.z << 2) + (pair << 1) + d2);
            cbs[d2] = cb;
            pp[d2] = ld7(PP0, cb, nb, sb, bb, tb, w4);
            bc[d2] = ld4(B, cb);
            sub_w64(pp[d2], W64, d, dB, dT, h, hS, hN, w4, &wmgc[d2]);
        }
        float acc0 = 0.f, acc1 = 0.f;
        #pragma unroll
        for (int d2 = 0; d2 < 2; ++d2) {
            float4 pw = westv(pp[d2]), pe = eastv(pp[d2]);
            float4 lap = pw + pe + pp[d2].n + pp[d2].s + pp[d2].b + pp[d2].t - 6.f * pp[d2].c;
            float4 rr = lap - bc[d2];
            st4(PP1, cbs[d2], pp[d2].c - make_float4(rr.x/(-6.f), rr.y/(-6.f), rr.z/(-6.f), rr.w/(-6.f)));
            acc0 += rr.x + rr.y;
            acc1 += rr.z + rr.w;
        }
        sred[threadIdx.y][threadIdx.x * 2]     = acc0;
        sred[threadIdx.y][threadIdx.x * 2 + 1] = acc1;
        __syncthreads();
        {
            int cw = tid & 63, chh = tid >> 6;
            float v = 0.125f * (sred[2 * chh][cw] + sred[2 * chh + 1][cw]);
            int dc = (blockIdx.z << 1) + pair, hc = (blockIdx.y << 2) + chh;
            Rp1[(dc * 64 + hc) * 64 + cw] = v;
            c64buf[pair][chh][cw] = v;
        }
        __syncthreads();
    }
    resid_tail(c64buf, c32buf, Rp2, Rp3, tid);
}

static __device__ __forceinline__ float mgcell(const float* __restrict__ Wp, int mc,
                                               float r, int d, int h, int w, int m)
{
    auto g = [&](int dd, int hh, int ww) -> float {
        if (dd < 0 || dd >= m || hh < 0 || hh >= m || ww < 0 || ww >= m) return 0.f;
        return Wp[((dd >> 1) * mc + (hh >> 1)) * mc + (ww >> 1)];
    };
    float wc = g(d, h, w);
    float lap = g(d-1,h,w) + g(d+1,h,w) + g(d,h-1,w) + g(d,h+1,w) + g(d,h,w-1) + g(d,h,w+1) - 6.f * wc;
    return wc - lap / (-6.f) + r / (-6.f);
}

static __device__ __forceinline__ float gpad(const float* __restrict__ W, int p1, int p2,
                                             int dd, int hh, int ww)
{
    return W[((dd >> 1) + 1) * p1 + ((hh >> 1) + 1) * p2 + ((ww >> 1) + 1)];
}
static __device__ __forceinline__ float mgpad(const float* __restrict__ W, int p1, int p2,
                                              float r, int d, int h, int w)
{
    float wc = gpad(W, p1, p2, d, h, w);
    float lap = gpad(W, p1, p2, d-1, h, w) + gpad(W, p1, p2, d+1, h, w)
              + gpad(W, p1, p2, d, h-1, w) + gpad(W, p1, p2, d, h+1, w)
              + gpad(W, p1, p2, d, h, w-1) + gpad(W, p1, p2, d, h, w+1) - 6.f * wc;
    return wc - lap / (-6.f) + r / (-6.f);
}

// ---------------------------------------------------------------------------
// Single-block coarse solver (1024 thr): R16 = Rp3[0]+Rp3[1], pyramid to 1,
// solve back up to W16. Levels <= 64 cells run entirely in warp 0 (syncwarp),
// shaving ~5 block-wide barriers off the dependency chain.
// ---------------------------------------------------------------------------
__global__ void __launch_bounds__(1024) k_coarse16(
    const float* __restrict__ Rp3, float* __restrict__ W16g, float* __restrict__ o_r)
{
    __shared__ float R16[4096], R8[512], R4[64], R2[8];
    __shared__ float W8p[1000], W4p[216], W2p[64], W1p[27];
    const int tid = threadIdx.x;

    if (tid < 1000) W8p[tid] = 0.f;
    if (tid < 216) W4p[tid] = 0.f;
    if (tid >= 256 && tid < 320) W2p[tid - 256] = 0.f;
    if (tid >= 512 && tid < 539) W1p[tid - 512] = 0.f;

    {
        const int k4 = tid << 2;
        float4 a = ld4(Rp3, k4);
        float4 b = ld4(Rp3, 4096 + k4);
        *reinterpret_cast<float4*>(R16 + k4) = a + b;
    }
    __syncthreads();
    if (tid < 512) {   // 16 -> 8
        int w = tid & 7, h = (tid >> 3) & 7, d = tid >> 6;
        int b0 = ((2 * d) * 16 + 2 * h) * 16 + 2 * w;
        R8[tid] = 0.125f * (R16[b0] + R16[b0+1] + R16[b0+16] + R16[b0+17]
                          + R16[b0+256] + R16[b0+257] + R16[b0+272] + R16[b0+273]);
    }
    __syncthreads();
    if (tid < 32) {    // warp 0 handles everything from R4 down and back to W4
        #pragma unroll
        for (int k = tid; k < 64; k += 32) {   // 8 -> 4
            int w = k & 3, h = (k >> 2) & 3, d = k >> 4;
            int b0 = ((2 * d) * 8 + 2 * h) * 8 + 2 * w;
            R4[k] = 0.125f * (R8[b0] + R8[b0+1] + R8[b0+8] + R8[b0+9]
                            + R8[b0+64] + R8[b0+65] + R8[b0+72] + R8[b0+73]);
        }
        __syncwarp();
        if (tid < 8) {     // 4 -> 2
            int w = tid & 1, h = (tid >> 1) & 1, d = tid >> 2;
            int b0 = ((2 * d) * 4 + 2 * h) * 4 + 2 * w;
            R2[tid] = 0.125f * (R4[b0] + R4[b0+1] + R4[b0+4] + R4[b0+5]
                              + R4[b0+16] + R4[b0+17] + R4[b0+20] + R4[b0+21]);
        }
        __syncwarp();
        if (tid == 0) {
            float r1 = 0.125f * (R2[0]+R2[1]+R2[2]+R2[3]+R2[4]+R2[5]+R2[6]+R2[7]);
            W1p[13] = r1 / (-6.f);
            if (o_r) o_r[0] = r1;
        }
        __syncwarp();
        if (tid < 8) {     // m = 2
            int w = tid & 1, h = (tid >> 1) & 1, d = tid >> 2;
            W2p[(d+1)*16 + (h+1)*4 + (w+1)] = mgpad(W1p, 9, 3, R2[tid], d, h, w);
        }
        __syncwarp();
        #pragma unroll
        for (int k = tid; k < 64; k += 32) {   // m = 4
            int w = k & 3, h = (k >> 2) & 3, d = k >> 4;
            W4p[(d+1)*36 + (h+1)*6 + (w+1)] = mgpad(W2p, 16, 4, R4[k], d, h, w);
        }
    }
    __syncthreads();
    if (tid < 512) {   // m = 8
        int w = tid & 7, h = (tid >> 3) & 7, d = tid >> 6;
        W8p[(d+1)*100 + (h+1)*10 + (w+1)] = mgpad(W4p, 36, 6, R8[tid], d, h, w);
    }
    __syncthreads();
    #pragma unroll
    for (int k = tid; k < 4096; k += 1024) {   // m = 16 -> global
        int w = k & 15, h = (k >> 4) & 15, d = k >> 8;
        W16g[k] = mgpad(W8p, 100, 10, R16[k], d, h, w);
    }
}

// ---------------------------------------------------------------------------
// Fused m=32 + m=64 MG levels. 1024 blocks x 256 thr. Each block computes its
// private 2x4x32 W32 slab in smem from W16+Rp2 (<=256 mgcell evals), then
// emits its 256 W64 cells. Replaces k_mg32 + k_w64.
// ---------------------------------------------------------------------------
__global__ void __launch_bounds__(256) k_mg64(
    const float* __restrict__ W16, const float* __restrict__ Rp2,
    const float* __restrict__ Rp1, float* __restrict__ W64)
{
    __shared__ float W32s[2][4][32];
    const int b = blockIdx.x;
    const int tid = threadIdx.x;
    const int d64 = b >> 4;
    const int H0  = (b & 15) << 2;

    const int dlo = (d64 > 0 ? d64 - 1 : 0) >> 1;
    const int dhi = (d64 < 63 ? d64 + 1 : 63) >> 1;
    const int h32base = (H0 > 0 ? H0 - 1 : 0) >> 1;

    {   // fill slab: 256 threads, one cell each
        const int w32 = tid & 31, hrow = (tid >> 5) & 3, dslot = tid >> 7;
        const int d32 = dslot ? dhi : dlo;
        const int h32 = h32base + hrow;
        float v = 0.f;
        if (h32 < 32)
            v = mgcell(W16, 16, Rp2[(d32 * 32 + h32) * 32 + w32], d32, h32, w32, 32);
        W32s[dslot][hrow][w32] = v;
    }
    __syncthreads();

    const int w = tid & 63;
    const int h64 = H0 + (tid >> 6);
    const int t = ((d64 << 6) + h64) * 64 + w;

    auto g = [&](int dd, int hh, int ww) -> float {
        if (dd < 0 || dd >= 64 || hh < 0 || hh >= 64 || ww < 0 || ww >= 64) return 0.f;
        const int d32 = dd >> 1;
        const int slot = (d32 == dlo) ? 0 : 1;
        return W32s[slot][(hh >> 1) - h32base][ww >> 1];
    };
    float wc = g(d64, h64, w);
    float lap = g(d64-1, h64, w) + g(d64+1, h64, w) + g(d64, h64-1, w) + g(d64, h64+1, w)
              + g(d64, h64, w-1) + g(d64, h64, w+1) - 6.f * wc;
    W64[t] = wc - lap / (-6.f) + Rp1[t] / (-6.f);
}

// ---------------------------------------------------------------------------
__global__ void __launch_bounds__(256) k_final2(
    const float* __restrict__ U1, const float* __restrict__ V1, const float* __restrict__ W1,
    const float* __restrict__ PP1, const float* __restrict__ W64,
    const float* __restrict__ SG, const float* __restrict__ DT,
    float* __restrict__ OU, float* __restrict__ OV, float* __restrict__ OW,
    float* __restrict__ OP, float* __restrict__ OWMG)
{
    const int w4 = threadIdx.x << 2;
    const int h  = (blockIdx.y << 3) + threadIdx.y;
    const int hS = cl(h - 1), hN = cl(h + 1);
    IDX6(blockIdx.z);

    S7 p = ld7(PP1, cb, nb, sb, bb, tb, w4);
    const float4 sg = ld4(SG, cb);
    const float4 u1 = ld4(U1, cb), v1 = ld4(V1, cb), w1 = ld4(W1, cb);
    const float dt = DT[0];

    float4 wmgc;
    sub_w64(p, W64, d, dB, dT, h, hS, hN, w4, &wmgc);

    const float4 fc = rcp4(dt, sg);
    float4 gpx = 0.5f * (eastv(p) - westv(p));
    float4 gpy = 0.5f * (p.n - p.s);
    float4 gpz = 0.5f * (p.t - p.b);
    st4(OU, cb, (u1 - dt * gpx) * fc);
    st4(OV, cb, (v1 - dt * gpy) * fc);
    st4(OW, cb, (w1 - dt * gpz) * fc);
    st4(OP, cb, p.c);
    st4(OWMG, cb, wmgc);
}

// ---------------------------------------------------------------------------
extern "C" void kernel_launch(void* const* d_in, const int* in_sizes, int n_in,
                              void* d_out, int out_size)
{
    const float* U  = (const float*)d_in[0];
    const float* V  = (const float*)d_in[1];
    const float* W_ = (const float*)d_in[2];
    const float* P  = (const float*)d_in[3];
    const float* SG = (const float*)d_in[4];
    const float* DT = (const float*)d_in[5];

    float* out   = (float*)d_out;
    float* o_u   = out;
    float* o_v   = out + (size_t)N3;
    float* o_w   = out + 2 * (size_t)N3;
    float* o_p   = out + 3 * (size_t)N3;
    float* o_wmg = out + 4 * (size_t)N3;
    float* o_r   = out + 5 * (size_t)N3;

    float* S = nullptr;
    cudaGetSymbolAddress((void**)&S, g_scratch);
    float* BU = S;
    float* BV = S + (size_t)N3;
    float* BW = S + 2 * (size_t)N3;
    float* U1 = S + 3 * (size_t)N3;
    float* V1 = S + 4 * (size_t)N3;
    float* W1 = S + 5 * (size_t)N3;
    float* B  = S + 6 * (size_t)N3;
    float* P1 = S + 7 * (size_t)N3;   // Ppre0
    float* P2 = S + 8 * (size_t)N3;   // Ppre1
    float* Rp1 = S + 9 * (size_t)N3;     // 64^3
    float* Rp2 = Rp1 + 262144;           // 32^3
    float* W16 = Rp2 + 32768;            // 16^3
    float* Rp3 = W16 + 4096;             // 2 x 16^3 split partials
    float* W64 = Rp3 + 8192;             // 64^3

    dim3 blkF(32, 4), grdF(1, 32, 128);     // fat kernels, 128 thr
    dim3 blkR(32, 8), grdR(1, 16, 32);      // residual (4 planes/block)
    dim3 grdP(1, 16, 128);

    k_predictor<<<grdF, blkF>>>(U, V, W_, P, SG, DT, BU, BV, BW);
    k_corrector<<<grdF, blkF>>>(BU, BV, BW, U, V, W_, P, SG, DT, U1, V1, W1);

    // iteration 0: Ppre0 -> P1; coarse chain -> W64_0
    k_residdiv<<<grdR, blkR>>>(P, U1, V1, W1, DT, B, P1, Rp1, Rp2, Rp3);
    k_coarse16<<<1, 1024>>>(Rp3, W16, nullptr);
    k_mg64<<<1024, 256>>>(W16, Rp2, Rp1, W64);

    // iteration 1: p1 = Ppre0 - W64_0 reconstructed inline; Ppre1 -> P2
    k_resid2<<<grdR, blkR>>>(P1, B, W64, P2, Rp1, Rp2, Rp3);
    k_coarse16<<<1, 1024>>>(Rp3, W16, o_r);
    k_mg64<<<1024, 256>>>(W16, Rp2, Rp1, W64);

    // final: p_final = Ppre1 - W64_1; velocity projection; o_p/o_wmg emitted here
    k_final2<<<grdP, blkR>>>(U1, V1, W1, P2, W64, SG, DT, o_u, o_v, o_w, o_p, o_wmg);
}